// round 8
// baseline (speedup 1.0000x reference)
#include <cuda_runtime.h>
#include <cuda_bf16.h>
#include <math.h>
#include <float.h>
#include <cstdint>

#define B 4096
#define T 200
#define BT (B*T)
#define GR 14   // batch rows per GRU block (grid 293 ~= 2 CTAs/SM)

// ---------------- scratch (device globals: no allocs allowed) ----------------
__device__ float g_xg[(size_t)BT * 128];
__device__ float g_xc[(size_t)BT * 64];
__device__ float g_rnn1[(size_t)BT * 64];
__device__ float g_alpha[BT];
__device__ float g_final2[B * 64];
// split-bf16 weights for the two projection GEMMs: layout [n(192)][k(64)]
__device__ __nv_bfloat16 g_bh1[192 * 64];
__device__ __nv_bfloat16 g_bl1[192 * 64];
__device__ __nv_bfloat16 g_bh2[192 * 64];
__device__ __nv_bfloat16 g_bl2[192 * 64];

__device__ __forceinline__ float sigmoidf_fast(float x) {
    return 1.0f / (1.0f + __expf(-x));
}
__device__ __forceinline__ float tanh_fast(float x) {
    float ax = fabsf(x);
    float e = __expf(-2.0f * ax);
    float th = __fdividef(1.0f - e, 1.0f + e);
    return copysignf(th, x);
}

__device__ __forceinline__ uint32_t smem_u32(const void* p) {
    uint32_t a;
    asm("{ .reg .u64 t; cvta.to.shared.u64 t, %1; cvt.u32.u64 %0, t; }" : "=r"(a) : "l"(p));
    return a;
}
__device__ __forceinline__ void ldsm_x4(uint32_t& r0, uint32_t& r1, uint32_t& r2, uint32_t& r3,
                                        uint32_t addr) {
    asm volatile("ldmatrix.sync.aligned.m8n8.x4.shared.b16 {%0,%1,%2,%3}, [%4];"
                 : "=r"(r0), "=r"(r1), "=r"(r2), "=r"(r3) : "r"(addr));
}
__device__ __forceinline__ void mma16816(float* c, const uint32_t* a, uint32_t b0, uint32_t b1) {
    asm volatile("mma.sync.aligned.m16n8k16.row.col.f32.bf16.bf16.f32 "
                 "{%0,%1,%2,%3}, {%4,%5,%6,%7}, {%8,%9}, {%0,%1,%2,%3};"
                 : "+f"(c[0]), "+f"(c[1]), "+f"(c[2]), "+f"(c[3])
                 : "r"(a[0]), "r"(a[1]), "r"(a[2]), "r"(a[3]), "r"(b0), "r"(b1));
}

// ---- packed f32x2 helpers ----
__device__ __forceinline__ uint64_t pack2(float lo, float hi) {
    uint64_t d; asm("mov.b64 %0, {%1,%2};" : "=l"(d) : "f"(lo), "f"(hi)); return d;
}
__device__ __forceinline__ void unpack2(uint64_t v, float& lo, float& hi) {
    asm("mov.b64 {%0,%1}, %2;" : "=f"(lo), "=f"(hi) : "l"(v));
}
__device__ __forceinline__ uint64_t dup2(float x) {
    uint64_t d; asm("mov.b64 %0, {%1,%1};" : "=l"(d) : "f"(x)); return d;
}
__device__ __forceinline__ void fma2(uint64_t& acc, uint64_t a, uint64_t b) {
    asm("fma.rn.f32x2 %0, %1, %2, %0;" : "+l"(acc) : "l"(a), "l"(b));
}
__device__ __forceinline__ void lds_v2_b64(uint64_t& a, uint64_t& b, uint32_t addr) {
    asm volatile("ld.shared.v2.b64 {%0,%1}, [%2];" : "=l"(a), "=l"(b) : "r"(addr));
}
__device__ __forceinline__ uint64_t lds_b64(uint32_t addr) {
    uint64_t a; asm volatile("ld.shared.b64 %0, [%1];" : "=l"(a) : "r"(addr)); return a;
}

// ======================================================================
// Weight split prep: W[64,128]|[64,64] fp32 -> Bhi/Blo [n=192][k=64] bf16
// ======================================================================
__global__ void wsplit_kernel(const float* __restrict__ Wg, const float* __restrict__ Wc,
                              __nv_bfloat16* __restrict__ Bhi, __nv_bfloat16* __restrict__ Blo)
{
    int idx = blockIdx.x * 256 + threadIdx.x;
    if (idx >= 192 * 64) return;
    int n = idx >> 6, k = idx & 63;
    float w = (n < 128) ? Wg[k * 128 + n] : Wc[k * 64 + (n - 128)];
    __nv_bfloat16 hi = __float2bfloat16(w);
    __nv_bfloat16 lo = __float2bfloat16(w - __bfloat162float(hi));
    Bhi[idx] = hi;
    Blo[idx] = lo;
}

// ======================================================================
// HMMA projection: D[128 x 192] = A[128x64] @ W + bias (unchanged, passing).
// ======================================================================
#define PAD_K 72   // bf16 elements per smem row (144 B)
#define PSM_BIAS 0
#define PSM_AHI  768
#define PSM_ALO  (PSM_AHI + 128 * PAD_K * 2)
#define PSM_BHI  (PSM_ALO + 128 * PAD_K * 2)
#define PSM_BLO  (PSM_BHI + 192 * PAD_K * 2)
#define PSM_TOTAL (PSM_BLO + 192 * PAD_K * 2)   // 92928 bytes

template<int MODE>
__global__ void __launch_bounds__(256, 2) proj_mma_kernel(
        const float* __restrict__ src,
        const int*   __restrict__ hist_i,
        const float* __restrict__ alpha,
        const __nv_bfloat16* __restrict__ Bhi,
        const __nv_bfloat16* __restrict__ Blo,
        const float* __restrict__ bg,
        const float* __restrict__ bc,
        float* __restrict__ xg,
        float* __restrict__ xc)
{
    extern __shared__ char smem[];
    const uint32_t sbase = smem_u32(smem);
    const int tid = threadIdx.x;
    const int wid = tid >> 5;
    const int lane = tid & 31;
    const int m0 = blockIdx.x * 128;

    float* bs = (float*)(smem + PSM_BIAS);
    if (tid < 192) bs[tid] = (tid < 128) ? bg[tid] : bc[tid - 128];

    {
        const uint4* sh = (const uint4*)Bhi;
        const uint4* sl = (const uint4*)Blo;
#pragma unroll
        for (int i = 0; i < 6; i++) {
            int idx = tid + 256 * i;               // < 1536
            int n = idx >> 3, seg = idx & 7;
            int off = n * (PAD_K * 2) + seg * 16;
            *(uint4*)(smem + PSM_BHI + off) = sh[idx];
            *(uint4*)(smem + PSM_BLO + off) = sl[idx];
        }
    }

    {
        const int r = tid >> 1;
        const int half = tid & 1;
        const float* srow;
        float scale = 1.0f;
        if (MODE == 0) {
            srow = src + (size_t)hist_i[m0 + r] * 64;
        } else {
            srow = src + (size_t)(m0 + r) * 64;
            scale = alpha[m0 + r];
        }
        srow += half * 32;
        const int kb = half * 32;
#pragma unroll
        for (int c = 0; c < 4; c++) {
            float4 v0 = *(const float4*)(srow + 8 * c);
            float4 v1 = *(const float4*)(srow + 8 * c + 4);
            float vv[8] = {v0.x, v0.y, v0.z, v0.w, v1.x, v1.y, v1.z, v1.w};
            __nv_bfloat16 hb[8], lb[8];
#pragma unroll
            for (int e = 0; e < 8; e++) {
                float f = vv[e] * scale;
                hb[e] = __float2bfloat16(f);
                lb[e] = __float2bfloat16(f - __bfloat162float(hb[e]));
            }
            int off = r * (PAD_K * 2) + (kb + 8 * c) * 2;
            *(uint4*)(smem + PSM_AHI + off) = *(uint4*)hb;
            *(uint4*)(smem + PSM_ALO + off) = *(uint4*)lb;
        }
    }
    __syncthreads();

    const int arow = wid * 16 + (lane & 15);
    const int acolb = ((lane >> 4) << 3);
    const uint32_t a_off = (uint32_t)arow * (PAD_K * 2) + acolb * 2;
    const uint32_t aH_base = sbase + PSM_AHI + a_off;
    const uint32_t aL_base = sbase + PSM_ALO + a_off;

    const int bnrow_l = (lane & 7) + ((lane & 16) >> 1);
    const int bcol_l = (lane & 8);
    const uint32_t b_off_l = (uint32_t)bnrow_l * (PAD_K * 2) + bcol_l * 2;

    const int g = lane >> 2;
    const int tq = lane & 3;

#pragma unroll
    for (int nh = 0; nh < 2; nh++) {
        const uint32_t bH_base = sbase + PSM_BHI + b_off_l + (uint32_t)nh * 96 * (PAD_K * 2);
        const uint32_t bL_base = sbase + PSM_BLO + b_off_l + (uint32_t)nh * 96 * (PAD_K * 2);

        float acc[12][4];
#pragma unroll
        for (int i = 0; i < 12; i++)
#pragma unroll
            for (int q = 0; q < 4; q++) acc[i][q] = 0.0f;

#pragma unroll
        for (int ks = 0; ks < 4; ks++) {
            uint32_t aH[4], aL[4];
            ldsm_x4(aH[0], aH[1], aH[2], aH[3], aH_base + ks * 32);
            ldsm_x4(aL[0], aL[1], aL[2], aL[3], aL_base + ks * 32);
#pragma unroll
            for (int np = 0; np < 6; np++) {
                uint32_t bh0, bh1, bh2, bh3;
                ldsm_x4(bh0, bh1, bh2, bh3,
                        bH_base + (uint32_t)np * 16 * (PAD_K * 2) + ks * 32);
                mma16816(acc[2 * np],     aH, bh0, bh1);
                mma16816(acc[2 * np + 1], aH, bh2, bh3);
                mma16816(acc[2 * np],     aL, bh0, bh1);
                mma16816(acc[2 * np + 1], aL, bh2, bh3);
                uint32_t bl0, bl1, bl2, bl3;
                ldsm_x4(bl0, bl1, bl2, bl3,
                        bL_base + (uint32_t)np * 16 * (PAD_K * 2) + ks * 32);
                mma16816(acc[2 * np],     aH, bl0, bl1);
                mma16816(acc[2 * np + 1], aH, bl2, bl3);
            }
        }

        const int r0 = m0 + wid * 16 + g;
        const int r1 = r0 + 8;
#pragma unroll
        for (int nt = 0; nt < 12; nt++) {
            const int n = nh * 96 + nt * 8 + 2 * tq;
            const float bx = bs[n], by = bs[n + 1];
            float2 o0 = make_float2(acc[nt][0] + bx, acc[nt][1] + by);
            float2 o1 = make_float2(acc[nt][2] + bx, acc[nt][3] + by);
            if (n < 128) {
                *(float2*)(xg + (size_t)r0 * 128 + n) = o0;
                *(float2*)(xg + (size_t)r1 * 128 + n) = o1;
            } else {
                *(float2*)(xc + (size_t)r0 * 64 + (n - 128)) = o0;
                *(float2*)(xc + (size_t)r1 * 64 + (n - 128)) = o1;
            }
        }
    }
}

// ======================================================================
// GRU recurrence v4: 128 threads x GR=14 rows, packed f32x2 math.
// States hs/rhs/zs laid out [hidden_k][20 floats] (7 row-pairs + pad),
// so ld.shared.v2.b64 feeds fma.rn.f32x2 directly (2 rows per FMA).
// ======================================================================
template<bool STORE_ALL>
__global__ void __launch_bounds__(128) gru_kernel(
                           const float* __restrict__ xg,
                           const float* __restrict__ xc,
                           const float* __restrict__ mask,
                           const float* __restrict__ Ug,  // [64,128]
                           const float* __restrict__ Uc,  // [64,64]
                           float* __restrict__ out)
{
    extern __shared__ float sm[];
    float* UgsT = sm;                  // [128][68]  UgsT[j][k]
    float* UcsT = UgsT + 128 * 68;     // [64][68]   UcsT[c][k]
    float* hs   = UcsT + 64 * 68;      // [64 k][20] rows 0..13 + pad
    float* rhs  = hs + 64 * 20;        // [64 k][20]
    float* zs   = rhs + 64 * 20;       // [64 c][20]
    float* msk  = zs + 64 * 20;        // [GR][T]

    const int j = threadIdx.x;         // 0..127
    const int b0 = blockIdx.x * GR;
    const int c = j >> 1;              // candidate column 0..63
    const int half = j & 1;

    for (int idx = j; idx < 128 * 64; idx += 128)
        UgsT[(idx & 127) * 68 + (idx >> 7)] = Ug[idx];
    for (int idx = j; idx < 64 * 64; idx += 128)
        UcsT[(idx & 63) * 68 + (idx >> 6)] = Uc[idx];
    for (int idx = j; idx < 64 * 20; idx += 128) hs[idx] = 0.0f;

    int br[GR];
#pragma unroll
    for (int r = 0; r < GR; r++) {
        int b = b0 + r;
        br[r] = (b < B) ? b : (B - 1);
    }
    for (int idx = j; idx < GR * T; idx += 128) {
        int r = idx / T, t = idx - r * T;
        msk[idx] = mask[(size_t)br[r] * T + t];
    }
    __syncthreads();

    const uint32_t hs_a  = smem_u32(hs);
    const uint32_t rhs_a = smem_u32(rhs);

    float xgv[GR];
#pragma unroll
    for (int r = 0; r < GR; r++)
        xgv[r] = xg[(size_t)br[r] * (T * 128) + j];

    const int rbase = half ? 8 : 0;
    const int nrows = half ? 6 : 8;
    const float* wg = UgsT + j * 68;
    const float* wc = UcsT + c * 68 + half * 32;

    for (int t = 0; t < T; t++) {
        // prefetch xc for this thread's update rows (hidden behind gate matvec)
        float xcv[8];
#pragma unroll
        for (int i = 0; i < 8; i++) {
            if (i < nrows)
                xcv[i] = xc[(size_t)br[rbase + i] * (T * 64) + t * 64 + c];
        }

        // ---- gate matvec (packed pairs) ----
        uint64_t acc2[7];
#pragma unroll
        for (int p = 0; p < 7; p++) acc2[p] = pack2(xgv[2 * p], xgv[2 * p + 1]);

#pragma unroll 4
        for (int k4 = 0; k4 < 16; k4++) {
            float4 w = *(const float4*)(wg + 4 * k4);
            float ws[4] = {w.x, w.y, w.z, w.w};
#pragma unroll
            for (int kk = 0; kk < 4; kk++) {
                uint32_t a = hs_a + (uint32_t)(4 * k4 + kk) * 80;
                uint64_t ww = dup2(ws[kk]);
                uint64_t p0, p1, p2, p3, p4, p5, p6;
                lds_v2_b64(p0, p1, a);
                lds_v2_b64(p2, p3, a + 16);
                lds_v2_b64(p4, p5, a + 32);
                p6 = lds_b64(a + 48);
                fma2(acc2[0], p0, ww); fma2(acc2[1], p1, ww);
                fma2(acc2[2], p2, ww); fma2(acc2[3], p3, ww);
                fma2(acc2[4], p4, ww); fma2(acc2[5], p5, ww);
                fma2(acc2[6], p6, ww);
            }
        }

        // prefetch next xg
        if (t + 1 < T) {
#pragma unroll
            for (int r = 0; r < GR; r++)
                xgv[r] = xg[(size_t)br[r] * (T * 128) + (t + 1) * 128 + j];
        }

        // gate epilogue
        {
            float gv[GR];
#pragma unroll
            for (int p = 0; p < 7; p++) unpack2(acc2[p], gv[2 * p], gv[2 * p + 1]);
            if (j < 64) {
#pragma unroll
                for (int r = 0; r < GR; r++) {
                    float g = sigmoidf_fast(gv[r]);
                    rhs[j * 20 + r] = g * hs[j * 20 + r];
                }
            } else {
                const int cz = j - 64;
#pragma unroll
                for (int r = 0; r < GR; r++)
                    zs[cz * 20 + r] = sigmoidf_fast(gv[r]);
            }
        }
        __syncthreads();

        // ---- candidate matvec (split-k across thread pairs, packed) ----
        uint64_t cacc2[7];
#pragma unroll
        for (int p = 0; p < 7; p++) cacc2[p] = 0;

#pragma unroll 4
        for (int k4 = 0; k4 < 8; k4++) {
            float4 w = *(const float4*)(wc + 4 * k4);
            float ws[4] = {w.x, w.y, w.z, w.w};
#pragma unroll
            for (int kk = 0; kk < 4; kk++) {
                uint32_t a = rhs_a + (uint32_t)(half * 32 + 4 * k4 + kk) * 80;
                uint64_t ww = dup2(ws[kk]);
                uint64_t p0, p1, p2, p3, p4, p5, p6;
                lds_v2_b64(p0, p1, a);
                lds_v2_b64(p2, p3, a + 16);
                lds_v2_b64(p4, p5, a + 32);
                p6 = lds_b64(a + 48);
                fma2(cacc2[0], p0, ww); fma2(cacc2[1], p1, ww);
                fma2(cacc2[2], p2, ww); fma2(cacc2[3], p3, ww);
                fma2(cacc2[4], p4, ww); fma2(cacc2[5], p5, ww);
                fma2(cacc2[6], p6, ww);
            }
        }

        // combine halves + state update (half0: rows 0-7, half1: rows 8-13)
        {
            float tv[GR];
#pragma unroll
            for (int p = 0; p < 7; p++) {
                float lo, hi;
                unpack2(cacc2[p], lo, hi);
                tv[2 * p]     = lo + __shfl_xor_sync(0xffffffffu, lo, 1);
                tv[2 * p + 1] = hi + __shfl_xor_sync(0xffffffffu, hi, 1);
            }
#pragma unroll
            for (int i = 0; i < 8; i++) {
                if (i < nrows) {
                    const int r = rbase + i;
                    float cand = tanh_fast(tv[r] + xcv[i]);
                    float z = zs[c * 20 + r];
                    float h = hs[c * 20 + r];
                    float hn = fmaf(z, h - cand, cand);
                    float m = msk[r * T + t];
                    float hnew = fmaf(m, hn - h, h);
                    hs[c * 20 + r] = hnew;
                    if (STORE_ALL && (b0 + r) < B)
                        out[(size_t)br[r] * (T * 64) + t * 64 + c] = hnew;
                }
            }
        }
        __syncthreads();
    }

    if (!STORE_ALL && j < 64) {
#pragma unroll
        for (int r = 0; r < GR; r++)
            if (b0 + r < B) out[(size_t)br[r] * 64 + j] = hs[j * 20 + r];
    }
}

// ======================================================================
// DIN attention (unchanged).
// ======================================================================
__global__ void __launch_bounds__(320) attn_kernel(
                            const int*   __restrict__ item_i,
                            const float* __restrict__ item_emb,
                            const float* __restrict__ rnn1,
                            const float* __restrict__ mask,
                            const float* __restrict__ Wa1, const float* __restrict__ ba1,
                            const float* __restrict__ Wa2, const float* __restrict__ ba2,
                            const float* __restrict__ Wa3, const float* __restrict__ ba3,
                            float* __restrict__ alpha)
{
    extern __shared__ float sm[];
    float* Weff = sm;
    float* base = Weff + 64 * 80;
    float* Wa2s = base + 80;
    float* ba2s = Wa2s + 80 * 40;
    float* Wa3s = ba2s + 40;
    float* qs   = Wa3s + 40;
    float* Ks   = qs + 64;
    float* d1s  = Ks + 32 * 68;
    float* d2s  = d1s + 32 * 80;
    float* sc   = d2s + 32 * 40;
    float* red  = sc + 224;

    const int b = blockIdx.x;
    const int tid = threadIdx.x;

    const int l1_t0 = (tid / 20) * 2;
    const int l1_c0 = (tid % 20) * 4;
    const int l2_t0 = (tid / 10) * 2;
    const int l2_c0 = (tid % 10) * 4;

    if (tid < 64) qs[tid] = item_emb[(size_t)item_i[b] * 64 + tid];
    __syncthreads();

    if (tid < 80) {
        int c = tid;
        float acc = ba1[c];
#pragma unroll 8
        for (int k = 0; k < 64; k++)
            acc = fmaf(qs[k], Wa1[k * 80 + c] + Wa1[(128 + k) * 80 + c], acc);
        base[c] = acc;
    }
    for (int idx = tid; idx < 64 * 80; idx += 320) {
        int k = idx / 80, c = idx - k * 80;
        Weff[idx] = Wa1[(64 + k) * 80 + c] - Wa1[(128 + k) * 80 + c]
                  + qs[k] * Wa1[(192 + k) * 80 + c];
    }
    for (int idx = tid; idx < 80 * 40; idx += 320) Wa2s[idx] = Wa2[idx];
    if (tid < 40) { ba2s[tid] = ba2[tid]; Wa3s[tid] = Wa3[tid]; }
    __syncthreads();

    const float ba3v = ba3[0];

    for (int cc = 0; cc < 7; cc++) {
        const int tt0 = cc * 32;

        for (int idx = tid; idx < 512; idx += 320) {
            int tl = idx >> 4, k4 = idx & 15;
            int tg = tt0 + tl; if (tg > T - 1) tg = T - 1;
            float4 v = *(const float4*)(rnn1 + ((size_t)b * T + tg) * 64 + 4 * k4);
            *(float4*)(Ks + tl * 68 + 4 * k4) = v;
        }
        __syncthreads();

        {
            float4 bse = *(const float4*)(base + l1_c0);
            float a00 = bse.x, a01 = bse.y, a02 = bse.z, a03 = bse.w;
            float a10 = bse.x, a11 = bse.y, a12 = bse.z, a13 = bse.w;
#pragma unroll 4
            for (int k4 = 0; k4 < 16; k4++) {
                float4 k0 = *(const float4*)(Ks + l1_t0 * 68 + 4 * k4);
                float4 k1 = *(const float4*)(Ks + (l1_t0 + 1) * 68 + 4 * k4);
                const float kk0[4] = {k0.x, k0.y, k0.z, k0.w};
                const float kk1[4] = {k1.x, k1.y, k1.z, k1.w};
#pragma unroll
                for (int kk = 0; kk < 4; kk++) {
                    float4 w = *(const float4*)(Weff + (4 * k4 + kk) * 80 + l1_c0);
                    a00 = fmaf(kk0[kk], w.x, a00); a01 = fmaf(kk0[kk], w.y, a01);
                    a02 = fmaf(kk0[kk], w.z, a02); a03 = fmaf(kk0[kk], w.w, a03);
                    a10 = fmaf(kk1[kk], w.x, a10); a11 = fmaf(kk1[kk], w.y, a11);
                    a12 = fmaf(kk1[kk], w.z, a12); a13 = fmaf(kk1[kk], w.w, a13);
                }
            }
            float4 o0 = make_float4(sigmoidf_fast(a00), sigmoidf_fast(a01),
                                    sigmoidf_fast(a02), sigmoidf_fast(a03));
            float4 o1 = make_float4(sigmoidf_fast(a10), sigmoidf_fast(a11),
                                    sigmoidf_fast(a12), sigmoidf_fast(a13));
            *(float4*)(d1s + l1_t0 * 80 + l1_c0) = o0;
            *(float4*)(d1s + (l1_t0 + 1) * 80 + l1_c0) = o1;
        }
        __syncthreads();

        if (tid < 160) {
            float4 bse = *(const float4*)(ba2s + l2_c0);
            float a00 = bse.x, a01 = bse.y, a02 = bse.z, a03 = bse.w;
            float a10 = bse.x, a11 = bse.y, a12 = bse.z, a13 = bse.w;
#pragma unroll 4
            for (int k4 = 0; k4 < 20; k4++) {
                float4 d0 = *(const float4*)(d1s + l2_t0 * 80 + 4 * k4);
                float4 d1 = *(const float4*)(d1s + (l2_t0 + 1) * 80 + 4 * k4);
                const float dd0[4] = {d0.x, d0.y, d0.z, d0.w};
                const float dd1[4] = {d1.x, d1.y, d1.z, d1.w};
#pragma unroll
                for (int kk = 0; kk < 4; kk++) {
                    float4 w = *(const float4*)(Wa2s + (4 * k4 + kk) * 40 + l2_c0);
                    a00 = fmaf(dd0[kk], w.x, a00); a01 = fmaf(dd0[kk], w.y, a01);
                    a02 = fmaf(dd0[kk], w.z, a02); a03 = fmaf(dd0[kk], w.w, a03);
                    a10 = fmaf(dd1[kk], w.x, a10); a11 = fmaf(dd1[kk], w.y, a11);
                    a12 = fmaf(dd1[kk], w.z, a12); a13 = fmaf(dd1[kk], w.w, a13);
                }
            }
            float4 o0 = make_float4(sigmoidf_fast(a00), sigmoidf_fast(a01),
                                    sigmoidf_fast(a02), sigmoidf_fast(a03));
            float4 o1 = make_float4(sigmoidf_fast(a10), sigmoidf_fast(a11),
                                    sigmoidf_fast(a12), sigmoidf_fast(a13));
            *(float4*)(d2s + l2_t0 * 40 + l2_c0) = o0;
            *(float4*)(d2s + (l2_t0 + 1) * 40 + l2_c0) = o1;
        }
        __syncthreads();

        if (tid < 32) {
            float acc = ba3v;
#pragma unroll
            for (int k4 = 0; k4 < 10; k4++) {
                float4 d = *(const float4*)(d2s + tid * 40 + 4 * k4);
                float4 w = *(const float4*)(Wa3s + 4 * k4);
                acc = fmaf(d.x, w.x, acc); acc = fmaf(d.y, w.y, acc);
                acc = fmaf(d.z, w.z, acc); acc = fmaf(d.w, w.w, acc);
            }
            int tg = tt0 + tid;
            if (tg < T) {
                float m = mask[(size_t)b * T + tg];
                sc[tg] = (m > 0.0f) ? acc : -1e9f;
            }
        }
        __syncthreads();
    }

    float v = (tid < T) ? sc[tid] : -FLT_MAX;
#pragma unroll
    for (int o = 16; o > 0; o >>= 1) v = fmaxf(v, __shfl_xor_sync(0xffffffffu, v, o));
    if ((tid & 31) == 0) red[tid >> 5] = v;
    __syncthreads();
    if (tid == 0) {
        float mx = red[0];
#pragma unroll
        for (int w = 1; w < 10; w++) mx = fmaxf(mx, red[w]);
        red[12] = mx;
    }
    __syncthreads();
    float mx = red[12];

    float e = (tid < T) ? __expf(sc[tid] - mx) : 0.0f;
    float s = e;
#pragma unroll
    for (int o = 16; o > 0; o >>= 1) s += __shfl_xor_sync(0xffffffffu, s, o);
    __syncthreads();
    if ((tid & 31) == 0) red[tid >> 5] = s;
    __syncthreads();
    if (tid == 0) {
        float sum = 0.0f;
#pragma unroll
        for (int w = 0; w < 10; w++) sum += red[w];
        red[13] = 1.0f / sum;
    }
    __syncthreads();
    if (tid < T) alpha[(size_t)b * T + tid] = e * red[13];
}

// ======================================================================
// FCN head + hist_sum (unchanged).
// ======================================================================
__global__ void fcn_kernel(const int* __restrict__ u, const int* __restrict__ ii,
                           const int* __restrict__ hist_i,
                           const float* __restrict__ item_emb,
                           const float* __restrict__ user_emb,
                           const float* __restrict__ final2,
                           const float* __restrict__ W1, const float* __restrict__ b1,
                           const float* __restrict__ p1,
                           const float* __restrict__ W2, const float* __restrict__ b2,
                           const float* __restrict__ p2,
                           const float* __restrict__ W3, const float* __restrict__ b3,
                           float* __restrict__ out)
{
    __shared__ float xs[320];
    __shared__ float h1s[128];
    __shared__ float h2s[40];

    const int b = blockIdx.x;
    const int tid = threadIdx.x;

    if (tid < 64) {
        const int* hi = hist_i + (size_t)b * T;
        float s0 = 0.f, s1 = 0.f, s2 = 0.f, s3 = 0.f;
        for (int t = 0; t < T; t += 4) {
            s0 += item_emb[(size_t)hi[t]     * 64 + tid];
            s1 += item_emb[(size_t)hi[t + 1] * 64 + tid];
            s2 += item_emb[(size_t)hi[t + 2] * 64 + tid];
            s3 += item_emb[(size_t)hi[t + 3] * 64 + tid];
        }
        xs[128 + tid] = (s0 + s1) + (s2 + s3);
    } else {
        int j = tid - 64;
        xs[j]       = user_emb[(size_t)u[b]  * 64 + j];
        xs[64 + j]  = item_emb[(size_t)ii[b] * 64 + j];
        xs[256 + j] = final2[(size_t)b * 64 + j];
    }
    __syncthreads();
    if (tid < 64) xs[192 + tid] = xs[64 + tid] * xs[128 + tid];
    __syncthreads();

    {
        float a0 = b1[tid], a1 = 0.0f;
#pragma unroll 8
        for (int k = 0; k < 320; k += 2) {
            a0 = fmaf(xs[k],     W1[k * 128 + tid],       a0);
            a1 = fmaf(xs[k + 1], W1[(k + 1) * 128 + tid], a1);
        }
        float h = a0 + a1;
        h1s[tid] = (h >= 0.0f) ? h : p1[tid] * h;
    }
    __syncthreads();

    if (tid < 40) {
        float a0 = b2[tid], a1 = 0.0f;
#pragma unroll 16
        for (int k = 0; k < 128; k += 2) {
            a0 = fmaf(h1s[k],     W2[k * 40 + tid],       a0);
            a1 = fmaf(h1s[k + 1], W2[(k + 1) * 40 + tid], a1);
        }
        float h = a0 + a1;
        h2s[tid] = (h >= 0.0f) ? h : p2[tid] * h;
    }
    __syncthreads();

    if (tid == 0) {
        float acc = b3[0];
#pragma unroll
        for (int k = 0; k < 40; k++) acc = fmaf(h2s[k], W3[k], acc);
        out[b] = acc;
    }
}

// ======================================================================
extern "C" void kernel_launch(void* const* d_in, const int* in_sizes, int n_in,
                              void* d_out, int out_size)
{
    const int*   u        = (const int*)d_in[0];
    const int*   ii       = (const int*)d_in[1];
    const int*   hist_i   = (const int*)d_in[2];
    const float* mask     = (const float*)d_in[3];
    const float* item_emb = (const float*)d_in[4];
    const float* user_emb = (const float*)d_in[5];
    const float* g1_Wg = (const float*)d_in[6];
    const float* g1_Ug = (const float*)d_in[7];
    const float* g1_bg = (const float*)d_in[8];
    const float* g1_Wc = (const float*)d_in[9];
    const float* g1_Uc = (const float*)d_in[10];
    const float* g1_bc = (const float*)d_in[11];
    const float* Wa1 = (const float*)d_in[12];
    const float* ba1 = (const float*)d_in[13];
    const float* Wa2 = (const float*)d_in[14];
    const float* ba2 = (const float*)d_in[15];
    const float* Wa3 = (const float*)d_in[16];
    const float* ba3 = (const float*)d_in[17];
    const float* g2_Wg = (const float*)d_in[18];
    const float* g2_Ug = (const float*)d_in[19];
    const float* g2_bg = (const float*)d_in[20];
    const float* g2_Wc = (const float*)d_in[21];
    const float* g2_Uc = (const float*)d_in[22];
    const float* g2_bc = (const float*)d_in[23];
    const float* W1 = (const float*)d_in[24];
    const float* b1 = (const float*)d_in[25];
    const float* p1 = (const float*)d_in[26];
    const float* W2 = (const float*)d_in[27];
    const float* b2 = (const float*)d_in[28];
    const float* p2 = (const float*)d_in[29];
    const float* W3 = (const float*)d_in[30];
    const float* b3 = (const float*)d_in[31];
    float* out = (float*)d_out;

    float *xg, *xc, *rnn1, *alpha, *final2;
    __nv_bfloat16 *bh1, *bl1, *bh2, *bl2;
    cudaGetSymbolAddress((void**)&xg,     g_xg);
    cudaGetSymbolAddress((void**)&xc,     g_xc);
    cudaGetSymbolAddress((void**)&rnn1,   g_rnn1);
    cudaGetSymbolAddress((void**)&alpha,  g_alpha);
    cudaGetSymbolAddress((void**)&final2, g_final2);
    cudaGetSymbolAddress((void**)&bh1, g_bh1);
    cudaGetSymbolAddress((void**)&bl1, g_bl1);
    cudaGetSymbolAddress((void**)&bh2, g_bh2);
    cudaGetSymbolAddress((void**)&bl2, g_bl2);

    const int GRU_SMEM  = (128 * 68 + 64 * 68 + 3 * 64 * 20 + GR * T) * 4;  // 78784
    const int ATTN_SMEM = (64*80 + 80 + 80*40 + 40 + 40 + 64
                         + 32*68 + 32*80 + 32*40 + 224 + 16) * 4;

    cudaFuncSetAttribute(proj_mma_kernel<0>, cudaFuncAttributeMaxDynamicSharedMemorySize, PSM_TOTAL);
    cudaFuncSetAttribute(proj_mma_kernel<1>, cudaFuncAttributeMaxDynamicSharedMemorySize, PSM_TOTAL);
    cudaFuncSetAttribute(gru_kernel<true>,  cudaFuncAttributeMaxDynamicSharedMemorySize, GRU_SMEM);
    cudaFuncSetAttribute(gru_kernel<false>, cudaFuncAttributeMaxDynamicSharedMemorySize, GRU_SMEM);
    cudaFuncSetAttribute(attn_kernel, cudaFuncAttributeMaxDynamicSharedMemorySize, ATTN_SMEM);

    const int GRU_GRID = (B + GR - 1) / GR;   // 293

    // 0) split projection weights to bf16 hi/lo (both GRUs)
    wsplit_kernel<<<48, 256>>>(g1_Wg, g1_Wc, bh1, bl1);
    wsplit_kernel<<<48, 256>>>(g2_Wg, g2_Wc, bh2, bl2);
    // 1) GRU1 input projections via HMMA tensor cores
    proj_mma_kernel<0><<<BT / 128, 256, PSM_TOTAL>>>(item_emb, hist_i, nullptr,
                                                     bh1, bl1, g1_bg, g1_bc, xg, xc);
    // 2) GRU1 recurrence -> rnn1
    gru_kernel<true><<<GRU_GRID, 128, GRU_SMEM>>>(xg, xc, mask, g1_Ug, g1_Uc, rnn1);
    // 3) DIN attention -> alpha
    attn_kernel<<<B, 320, ATTN_SMEM>>>(ii, item_emb, rnn1, mask,
                                       Wa1, ba1, Wa2, ba2, Wa3, ba3, alpha);
    // 4) GRU2 input projections via HMMA (rnn1 * alpha)
    proj_mma_kernel<1><<<BT / 128, 256, PSM_TOTAL>>>(rnn1, nullptr, alpha,
                                                     bh2, bl2, g2_bg, g2_bc, xg, xc);
    // 5) GRU2 recurrence -> final2 only
    gru_kernel<false><<<GRU_GRID, 128, GRU_SMEM>>>(xg, xc, mask, g2_Ug, g2_Uc, final2);
    // 6) FCN head -> logits
    fcn_kernel<<<B, 128>>>(u, ii, hist_i, item_emb, user_emb, final2,
                           W1, b1, p1, W2, b2, p2, W3, b3, out);
}

// round 9
// speedup vs baseline: 1.0216x; 1.0216x over previous
#include <cuda_runtime.h>
#include <cuda_bf16.h>
#include <math.h>
#include <float.h>
#include <cstdint>

#define B 4096
#define T 200
#define BT (B*T)
#define GR 10   // batch rows per GRU block (5 row-pairs), grid 410

// ---------------- scratch (device globals: no allocs allowed) ----------------
__device__ float g_xg[(size_t)BT * 128];
__device__ float g_xc[(size_t)BT * 64];
__device__ float g_rnn1[(size_t)BT * 64];
__device__ float g_alpha[BT];
__device__ float g_final2[B * 64];
// split-bf16 weights for the two projection GEMMs: layout [n(192)][k(64)]
__device__ __nv_bfloat16 g_bh1[192 * 64];
__device__ __nv_bfloat16 g_bl1[192 * 64];
__device__ __nv_bfloat16 g_bh2[192 * 64];
__device__ __nv_bfloat16 g_bl2[192 * 64];

__device__ __forceinline__ float sigmoidf_fast(float x) {
    return 1.0f / (1.0f + __expf(-x));
}
__device__ __forceinline__ float tanh_fast(float x) {
    float ax = fabsf(x);
    float e = __expf(-2.0f * ax);
    float th = __fdividef(1.0f - e, 1.0f + e);
    return copysignf(th, x);
}

__device__ __forceinline__ uint32_t smem_u32(const void* p) {
    uint32_t a;
    asm("{ .reg .u64 t; cvta.to.shared.u64 t, %1; cvt.u32.u64 %0, t; }" : "=r"(a) : "l"(p));
    return a;
}
__device__ __forceinline__ void ldsm_x4(uint32_t& r0, uint32_t& r1, uint32_t& r2, uint32_t& r3,
                                        uint32_t addr) {
    asm volatile("ldmatrix.sync.aligned.m8n8.x4.shared.b16 {%0,%1,%2,%3}, [%4];"
                 : "=r"(r0), "=r"(r1), "=r"(r2), "=r"(r3) : "r"(addr));
}
__device__ __forceinline__ void mma16816(float* c, const uint32_t* a, uint32_t b0, uint32_t b1) {
    asm volatile("mma.sync.aligned.m16n8k16.row.col.f32.bf16.bf16.f32 "
                 "{%0,%1,%2,%3}, {%4,%5,%6,%7}, {%8,%9}, {%0,%1,%2,%3};"
                 : "+f"(c[0]), "+f"(c[1]), "+f"(c[2]), "+f"(c[3])
                 : "r"(a[0]), "r"(a[1]), "r"(a[2]), "r"(a[3]), "r"(b0), "r"(b1));
}

// ---- packed f32x2 helpers ----
__device__ __forceinline__ uint64_t pack2(float lo, float hi) {
    uint64_t d; asm("mov.b64 %0, {%1,%2};" : "=l"(d) : "f"(lo), "f"(hi)); return d;
}
__device__ __forceinline__ void unpack2(uint64_t v, float& lo, float& hi) {
    asm("mov.b64 {%0,%1}, %2;" : "=f"(lo), "=f"(hi) : "l"(v));
}
__device__ __forceinline__ uint64_t dup2(float x) {
    uint64_t d; asm("mov.b64 %0, {%1,%1};" : "=l"(d) : "f"(x)); return d;
}
__device__ __forceinline__ void fma2(uint64_t& acc, uint64_t a, uint64_t b) {
    asm("fma.rn.f32x2 %0, %1, %2, %0;" : "+l"(acc) : "l"(a), "l"(b));
}
__device__ __forceinline__ void lds_v2_b64(uint64_t& a, uint64_t& b, uint32_t addr) {
    asm volatile("ld.shared.v2.b64 {%0,%1}, [%2];" : "=l"(a), "=l"(b) : "r"(addr));
}
__device__ __forceinline__ uint64_t lds_b64(uint32_t addr) {
    uint64_t a; asm volatile("ld.shared.b64 %0, [%1];" : "=l"(a) : "r"(addr)); return a;
}
__device__ __forceinline__ void sts_b64(uint32_t addr, uint64_t v) {
    asm volatile("st.shared.b64 [%0], %1;" :: "r"(addr), "l"(v) : "memory");
}

// ======================================================================
// Weight split prep: W[64,128]|[64,64] fp32 -> Bhi/Blo [n=192][k=64] bf16
// ======================================================================
__global__ void wsplit_kernel(const float* __restrict__ Wg, const float* __restrict__ Wc,
                              __nv_bfloat16* __restrict__ Bhi, __nv_bfloat16* __restrict__ Blo)
{
    int idx = blockIdx.x * 256 + threadIdx.x;
    if (idx >= 192 * 64) return;
    int n = idx >> 6, k = idx & 63;
    float w = (n < 128) ? Wg[k * 128 + n] : Wc[k * 64 + (n - 128)];
    __nv_bfloat16 hi = __float2bfloat16(w);
    __nv_bfloat16 lo = __float2bfloat16(w - __bfloat162float(hi));
    Bhi[idx] = hi;
    Blo[idx] = lo;
}

// ======================================================================
// HMMA projection: D[128 x 192] = A[128x64] @ W + bias (unchanged, passing).
// ======================================================================
#define PAD_K 72   // bf16 elements per smem row (144 B)
#define PSM_BIAS 0
#define PSM_AHI  768
#define PSM_ALO  (PSM_AHI + 128 * PAD_K * 2)
#define PSM_BHI  (PSM_ALO + 128 * PAD_K * 2)
#define PSM_BLO  (PSM_BHI + 192 * PAD_K * 2)
#define PSM_TOTAL (PSM_BLO + 192 * PAD_K * 2)   // 92928 bytes

template<int MODE>
__global__ void __launch_bounds__(256, 2) proj_mma_kernel(
        const float* __restrict__ src,
        const int*   __restrict__ hist_i,
        const float* __restrict__ alpha,
        const __nv_bfloat16* __restrict__ Bhi,
        const __nv_bfloat16* __restrict__ Blo,
        const float* __restrict__ bg,
        const float* __restrict__ bc,
        float* __restrict__ xg,
        float* __restrict__ xc)
{
    extern __shared__ char smem[];
    const uint32_t sbase = smem_u32(smem);
    const int tid = threadIdx.x;
    const int wid = tid >> 5;
    const int lane = tid & 31;
    const int m0 = blockIdx.x * 128;

    float* bs = (float*)(smem + PSM_BIAS);
    if (tid < 192) bs[tid] = (tid < 128) ? bg[tid] : bc[tid - 128];

    {
        const uint4* sh = (const uint4*)Bhi;
        const uint4* sl = (const uint4*)Blo;
#pragma unroll
        for (int i = 0; i < 6; i++) {
            int idx = tid + 256 * i;               // < 1536
            int n = idx >> 3, seg = idx & 7;
            int off = n * (PAD_K * 2) + seg * 16;
            *(uint4*)(smem + PSM_BHI + off) = sh[idx];
            *(uint4*)(smem + PSM_BLO + off) = sl[idx];
        }
    }

    {
        const int r = tid >> 1;
        const int half = tid & 1;
        const float* srow;
        float scale = 1.0f;
        if (MODE == 0) {
            srow = src + (size_t)hist_i[m0 + r] * 64;
        } else {
            srow = src + (size_t)(m0 + r) * 64;
            scale = alpha[m0 + r];
        }
        srow += half * 32;
        const int kb = half * 32;
#pragma unroll
        for (int c = 0; c < 4; c++) {
            float4 v0 = *(const float4*)(srow + 8 * c);
            float4 v1 = *(const float4*)(srow + 8 * c + 4);
            float vv[8] = {v0.x, v0.y, v0.z, v0.w, v1.x, v1.y, v1.z, v1.w};
            __nv_bfloat16 hb[8], lb[8];
#pragma unroll
            for (int e = 0; e < 8; e++) {
                float f = vv[e] * scale;
                hb[e] = __float2bfloat16(f);
                lb[e] = __float2bfloat16(f - __bfloat162float(hb[e]));
            }
            int off = r * (PAD_K * 2) + (kb + 8 * c) * 2;
            *(uint4*)(smem + PSM_AHI + off) = *(uint4*)hb;
            *(uint4*)(smem + PSM_ALO + off) = *(uint4*)lb;
        }
    }
    __syncthreads();

    const int arow = wid * 16 + (lane & 15);
    const int acolb = ((lane >> 4) << 3);
    const uint32_t a_off = (uint32_t)arow * (PAD_K * 2) + acolb * 2;
    const uint32_t aH_base = sbase + PSM_AHI + a_off;
    const uint32_t aL_base = sbase + PSM_ALO + a_off;

    const int bnrow_l = (lane & 7) + ((lane & 16) >> 1);
    const int bcol_l = (lane & 8);
    const uint32_t b_off_l = (uint32_t)bnrow_l * (PAD_K * 2) + bcol_l * 2;

    const int g = lane >> 2;
    const int tq = lane & 3;

#pragma unroll
    for (int nh = 0; nh < 2; nh++) {
        const uint32_t bH_base = sbase + PSM_BHI + b_off_l + (uint32_t)nh * 96 * (PAD_K * 2);
        const uint32_t bL_base = sbase + PSM_BLO + b_off_l + (uint32_t)nh * 96 * (PAD_K * 2);

        float acc[12][4];
#pragma unroll
        for (int i = 0; i < 12; i++)
#pragma unroll
            for (int q = 0; q < 4; q++) acc[i][q] = 0.0f;

#pragma unroll
        for (int ks = 0; ks < 4; ks++) {
            uint32_t aH[4], aL[4];
            ldsm_x4(aH[0], aH[1], aH[2], aH[3], aH_base + ks * 32);
            ldsm_x4(aL[0], aL[1], aL[2], aL[3], aL_base + ks * 32);
#pragma unroll
            for (int np = 0; np < 6; np++) {
                uint32_t bh0, bh1, bh2, bh3;
                ldsm_x4(bh0, bh1, bh2, bh3,
                        bH_base + (uint32_t)np * 16 * (PAD_K * 2) + ks * 32);
                mma16816(acc[2 * np],     aH, bh0, bh1);
                mma16816(acc[2 * np + 1], aH, bh2, bh3);
                mma16816(acc[2 * np],     aL, bh0, bh1);
                mma16816(acc[2 * np + 1], aL, bh2, bh3);
                uint32_t bl0, bl1, bl2, bl3;
                ldsm_x4(bl0, bl1, bl2, bl3,
                        bL_base + (uint32_t)np * 16 * (PAD_K * 2) + ks * 32);
                mma16816(acc[2 * np],     aH, bl0, bl1);
                mma16816(acc[2 * np + 1], aH, bl2, bl3);
            }
        }

        const int r0 = m0 + wid * 16 + g;
        const int r1 = r0 + 8;
#pragma unroll
        for (int nt = 0; nt < 12; nt++) {
            const int n = nh * 96 + nt * 8 + 2 * tq;
            const float bx = bs[n], by = bs[n + 1];
            float2 o0 = make_float2(acc[nt][0] + bx, acc[nt][1] + by);
            float2 o1 = make_float2(acc[nt][2] + bx, acc[nt][3] + by);
            if (n < 128) {
                *(float2*)(xg + (size_t)r0 * 128 + n) = o0;
                *(float2*)(xg + (size_t)r1 * 128 + n) = o1;
            } else {
                *(float2*)(xc + (size_t)r0 * 64 + (n - 128)) = o0;
                *(float2*)(xc + (size_t)r1 * 64 + (n - 128)) = o1;
            }
        }
    }
}

// ======================================================================
// GRU recurrence v5: 128 threads x GR=10 rows, packed f32x2 math with
// row-pair-major state layout [pair][k][2]:
//   - all matvec reads are BROADCAST ld.shared.v2.b64 (conflict-free)
//   - each fma.rn.f32x2 does 2 rows at once (half the FMA issue count)
//   - candidate split-k across thread pairs, combined with one 64-bit shfl
// ======================================================================
#define NP (GR/2)   // 5 row-pairs
template<bool STORE_ALL>
__global__ void __launch_bounds__(128) gru_kernel(
                           const float* __restrict__ xg,
                           const float* __restrict__ xc,
                           const float* __restrict__ mask,
                           const float* __restrict__ Ug,  // [64,128]
                           const float* __restrict__ Uc,  // [64,64]
                           float* __restrict__ out)
{
    extern __shared__ float sm[];
    float* UgsT = sm;                   // [128][68]  UgsT[j][k]
    float* UcsT = UgsT + 128 * 68;      // [64][68]   UcsT[c][k]
    float* hs   = UcsT + 64 * 68;       // [NP][64][2]
    float* rhs  = hs + NP * 128;        // [NP][64][2]
    float* zs   = rhs + NP * 128;       // [NP][64][2]
    float* msk  = zs + NP * 128;        // [GR][T]

    const int j = threadIdx.x;          // 0..127
    const int b0 = blockIdx.x * GR;
    const int c = j >> 1;               // candidate column 0..63
    const int half = j & 1;

    for (int idx = j; idx < 128 * 64; idx += 128)
        UgsT[(idx & 127) * 68 + (idx >> 7)] = Ug[idx];
    for (int idx = j; idx < 64 * 64; idx += 128)
        UcsT[(idx & 63) * 68 + (idx >> 6)] = Uc[idx];
    for (int idx = j; idx < NP * 128; idx += 128) hs[idx] = 0.0f;

    int br[GR];
#pragma unroll
    for (int r = 0; r < GR; r++) {
        int b = b0 + r;
        br[r] = (b < B) ? b : (B - 1);
    }
    for (int idx = j; idx < GR * T; idx += 128) {
        int r = idx / T, t = idx - r * T;
        msk[idx] = mask[(size_t)br[r] * T + t];
    }
    __syncthreads();

    const uint32_t hs_a  = smem_u32(hs);
    const uint32_t rhs_a = smem_u32(rhs);
    const uint32_t zs_a  = smem_u32(zs);

    float xgv[GR];
#pragma unroll
    for (int r = 0; r < GR; r++)
        xgv[r] = xg[(size_t)br[r] * (T * 128) + j];

    const float* wg = UgsT + j * 68;
    const float* wc = UcsT + c * 68 + half * 32;
    const uint64_t one2 = dup2(1.0f);

    for (int t = 0; t < T; t++) {
        // prefetch xc for this thread's 5 update rows (rows 2p+half)
        float xcv[NP];
#pragma unroll
        for (int p = 0; p < NP; p++)
            xcv[p] = xc[(size_t)br[2 * p + half] * (T * 64) + t * 64 + c];

        // ---- gate matvec: acc2[p] packs rows (2p, 2p+1) ----
        uint64_t acc2[NP];
#pragma unroll
        for (int p = 0; p < NP; p++) acc2[p] = pack2(xgv[2 * p], xgv[2 * p + 1]);

#pragma unroll 4
        for (int k4 = 0; k4 < 16; k4++) {
            float4 w = *(const float4*)(wg + 4 * k4);
            uint64_t w0 = dup2(w.x), w1 = dup2(w.y), w2 = dup2(w.z), w3 = dup2(w.w);
#pragma unroll
            for (int p = 0; p < NP; p++) {
                uint32_t a = hs_a + (uint32_t)p * 512 + (uint32_t)k4 * 32;
                uint64_t h0, h1, h2, h3;
                lds_v2_b64(h0, h1, a);
                lds_v2_b64(h2, h3, a + 16);
                fma2(acc2[p], h0, w0);
                fma2(acc2[p], h1, w1);
                fma2(acc2[p], h2, w2);
                fma2(acc2[p], h3, w3);
            }
        }

        // prefetch next xg
        if (t + 1 < T) {
#pragma unroll
            for (int r = 0; r < GR; r++)
                xgv[r] = xg[(size_t)br[r] * (T * 128) + (t + 1) * 128 + j];
        }

        // ---- gate epilogue ----
        if (j < 64) {
#pragma unroll
            for (int p = 0; p < NP; p++) {
                float g0, g1;
                unpack2(acc2[p], g0, g1);
                float h0, h1;
                unpack2(lds_b64(hs_a + (uint32_t)p * 512 + (uint32_t)j * 8), h0, h1);
                sts_b64(rhs_a + (uint32_t)p * 512 + (uint32_t)j * 8,
                        pack2(sigmoidf_fast(g0) * h0, sigmoidf_fast(g1) * h1));
            }
        } else {
            const int cz = j - 64;
#pragma unroll
            for (int p = 0; p < NP; p++) {
                float g0, g1;
                unpack2(acc2[p], g0, g1);
                sts_b64(zs_a + (uint32_t)p * 512 + (uint32_t)cz * 8,
                        pack2(sigmoidf_fast(g0), sigmoidf_fast(g1)));
            }
        }
        __syncthreads();

        // ---- candidate matvec (split-k across thread pairs, packed) ----
        uint64_t cacc2[NP];
#pragma unroll
        for (int p = 0; p < NP; p++) cacc2[p] = 0;

#pragma unroll 4
        for (int k4 = 0; k4 < 8; k4++) {
            float4 w = *(const float4*)(wc + 4 * k4);
            uint64_t w0 = dup2(w.x), w1 = dup2(w.y), w2 = dup2(w.z), w3 = dup2(w.w);
#pragma unroll
            for (int p = 0; p < NP; p++) {
                uint32_t a = rhs_a + (uint32_t)p * 512 + (uint32_t)half * 256
                           + (uint32_t)k4 * 32;
                uint64_t r0, r1, r2, r3;
                lds_v2_b64(r0, r1, a);
                lds_v2_b64(r2, r3, a + 16);
                fma2(cacc2[p], r0, w0);
                fma2(cacc2[p], r1, w1);
                fma2(cacc2[p], r2, w2);
                fma2(cacc2[p], r3, w3);
            }
        }

        // ---- combine halves (64-bit shfl) + state update ----
#pragma unroll
        for (int p = 0; p < NP; p++) {
            uint64_t other = __shfl_xor_sync(0xffffffffu, (unsigned long long)cacc2[p], 1);
            fma2(cacc2[p], other, one2);   // cacc2[p] += other (packed add)
            float lo, hi;
            unpack2(cacc2[p], lo, hi);
            const int rr = 2 * p + half;
            float tot = half ? hi : lo;
            float cand = tanh_fast(tot + xcv[p]);
            uint32_t soff = (uint32_t)p * 512 + (uint32_t)c * 8 + (uint32_t)half * 4;
            float z = *(const float*)((const char*)zs + soff);
            float h = *(const float*)((const char*)hs + soff);
            float hn = fmaf(z, h - cand, cand);
            float m = msk[rr * T + t];
            float hnew = fmaf(m, hn - h, h);
            *(float*)((char*)hs + soff) = hnew;
            if (STORE_ALL && (b0 + rr) < B)
                out[(size_t)br[rr] * (T * 64) + t * 64 + c] = hnew;
        }
        __syncthreads();
    }

    if (!STORE_ALL && j < 64) {
#pragma unroll
        for (int p = 0; p < NP; p++) {
            float h0, h1;
            unpack2(lds_b64(hs_a + (uint32_t)p * 512 + (uint32_t)j * 8), h0, h1);
            if (b0 + 2 * p < B)     out[(size_t)br[2 * p] * 64 + j] = h0;
            if (b0 + 2 * p + 1 < B) out[(size_t)br[2 * p + 1] * 64 + j] = h1;
        }
    }
}

// ======================================================================
// DIN attention (unchanged).
// ======================================================================
__global__ void __launch_bounds__(320) attn_kernel(
                            const int*   __restrict__ item_i,
                            const float* __restrict__ item_emb,
                            const float* __restrict__ rnn1,
                            const float* __restrict__ mask,
                            const float* __restrict__ Wa1, const float* __restrict__ ba1,
                            const float* __restrict__ Wa2, const float* __restrict__ ba2,
                            const float* __restrict__ Wa3, const float* __restrict__ ba3,
                            float* __restrict__ alpha)
{
    extern __shared__ float sm[];
    float* Weff = sm;
    float* base = Weff + 64 * 80;
    float* Wa2s = base + 80;
    float* ba2s = Wa2s + 80 * 40;
    float* Wa3s = ba2s + 40;
    float* qs   = Wa3s + 40;
    float* Ks   = qs + 64;
    float* d1s  = Ks + 32 * 68;
    float* d2s  = d1s + 32 * 80;
    float* sc   = d2s + 32 * 40;
    float* red  = sc + 224;

    const int b = blockIdx.x;
    const int tid = threadIdx.x;

    const int l1_t0 = (tid / 20) * 2;
    const int l1_c0 = (tid % 20) * 4;
    const int l2_t0 = (tid / 10) * 2;
    const int l2_c0 = (tid % 10) * 4;

    if (tid < 64) qs[tid] = item_emb[(size_t)item_i[b] * 64 + tid];
    __syncthreads();

    if (tid < 80) {
        int c = tid;
        float acc = ba1[c];
#pragma unroll 8
        for (int k = 0; k < 64; k++)
            acc = fmaf(qs[k], Wa1[k * 80 + c] + Wa1[(128 + k) * 80 + c], acc);
        base[c] = acc;
    }
    for (int idx = tid; idx < 64 * 80; idx += 320) {
        int k = idx / 80, c = idx - k * 80;
        Weff[idx] = Wa1[(64 + k) * 80 + c] - Wa1[(128 + k) * 80 + c]
                  + qs[k] * Wa1[(192 + k) * 80 + c];
    }
    for (int idx = tid; idx < 80 * 40; idx += 320) Wa2s[idx] = Wa2[idx];
    if (tid < 40) { ba2s[tid] = ba2[tid]; Wa3s[tid] = Wa3[tid]; }
    __syncthreads();

    const float ba3v = ba3[0];

    for (int cc = 0; cc < 7; cc++) {
        const int tt0 = cc * 32;

        for (int idx = tid; idx < 512; idx += 320) {
            int tl = idx >> 4, k4 = idx & 15;
            int tg = tt0 + tl; if (tg > T - 1) tg = T - 1;
            float4 v = *(const float4*)(rnn1 + ((size_t)b * T + tg) * 64 + 4 * k4);
            *(float4*)(Ks + tl * 68 + 4 * k4) = v;
        }
        __syncthreads();

        {
            float4 bse = *(const float4*)(base + l1_c0);
            float a00 = bse.x, a01 = bse.y, a02 = bse.z, a03 = bse.w;
            float a10 = bse.x, a11 = bse.y, a12 = bse.z, a13 = bse.w;
#pragma unroll 4
            for (int k4 = 0; k4 < 16; k4++) {
                float4 k0 = *(const float4*)(Ks + l1_t0 * 68 + 4 * k4);
                float4 k1 = *(const float4*)(Ks + (l1_t0 + 1) * 68 + 4 * k4);
                const float kk0[4] = {k0.x, k0.y, k0.z, k0.w};
                const float kk1[4] = {k1.x, k1.y, k1.z, k1.w};
#pragma unroll
                for (int kk = 0; kk < 4; kk++) {
                    float4 w = *(const float4*)(Weff + (4 * k4 + kk) * 80 + l1_c0);
                    a00 = fmaf(kk0[kk], w.x, a00); a01 = fmaf(kk0[kk], w.y, a01);
                    a02 = fmaf(kk0[kk], w.z, a02); a03 = fmaf(kk0[kk], w.w, a03);
                    a10 = fmaf(kk1[kk], w.x, a10); a11 = fmaf(kk1[kk], w.y, a11);
                    a12 = fmaf(kk1[kk], w.z, a12); a13 = fmaf(kk1[kk], w.w, a13);
                }
            }
            float4 o0 = make_float4(sigmoidf_fast(a00), sigmoidf_fast(a01),
                                    sigmoidf_fast(a02), sigmoidf_fast(a03));
            float4 o1 = make_float4(sigmoidf_fast(a10), sigmoidf_fast(a11),
                                    sigmoidf_fast(a12), sigmoidf_fast(a13));
            *(float4*)(d1s + l1_t0 * 80 + l1_c0) = o0;
            *(float4*)(d1s + (l1_t0 + 1) * 80 + l1_c0) = o1;
        }
        __syncthreads();

        if (tid < 160) {
            float4 bse = *(const float4*)(ba2s + l2_c0);
            float a00 = bse.x, a01 = bse.y, a02 = bse.z, a03 = bse.w;
            float a10 = bse.x, a11 = bse.y, a12 = bse.z, a13 = bse.w;
#pragma unroll 4
            for (int k4 = 0; k4 < 20; k4++) {
                float4 d0 = *(const float4*)(d1s + l2_t0 * 80 + 4 * k4);
                float4 d1 = *(const float4*)(d1s + (l2_t0 + 1) * 80 + 4 * k4);
                const float dd0[4] = {d0.x, d0.y, d0.z, d0.w};
                const float dd1[4] = {d1.x, d1.y, d1.z, d1.w};
#pragma unroll
                for (int kk = 0; kk < 4; kk++) {
                    float4 w = *(const float4*)(Wa2s + (4 * k4 + kk) * 40 + l2_c0);
                    a00 = fmaf(dd0[kk], w.x, a00); a01 = fmaf(dd0[kk], w.y, a01);
                    a02 = fmaf(dd0[kk], w.z, a02); a03 = fmaf(dd0[kk], w.w, a03);
                    a10 = fmaf(dd1[kk], w.x, a10); a11 = fmaf(dd1[kk], w.y, a11);
                    a12 = fmaf(dd1[kk], w.z, a12); a13 = fmaf(dd1[kk], w.w, a13);
                }
            }
            float4 o0 = make_float4(sigmoidf_fast(a00), sigmoidf_fast(a01),
                                    sigmoidf_fast(a02), sigmoidf_fast(a03));
            float4 o1 = make_float4(sigmoidf_fast(a10), sigmoidf_fast(a11),
                                    sigmoidf_fast(a12), sigmoidf_fast(a13));
            *(float4*)(d2s + l2_t0 * 40 + l2_c0) = o0;
            *(float4*)(d2s + (l2_t0 + 1) * 40 + l2_c0) = o1;
        }
        __syncthreads();

        if (tid < 32) {
            float acc = ba3v;
#pragma unroll
            for (int k4 = 0; k4 < 10; k4++) {
                float4 d = *(const float4*)(d2s + tid * 40 + 4 * k4);
                float4 w = *(const float4*)(Wa3s + 4 * k4);
                acc = fmaf(d.x, w.x, acc); acc = fmaf(d.y, w.y, acc);
                acc = fmaf(d.z, w.z, acc); acc = fmaf(d.w, w.w, acc);
            }
            int tg = tt0 + tid;
            if (tg < T) {
                float m = mask[(size_t)b * T + tg];
                sc[tg] = (m > 0.0f) ? acc : -1e9f;
            }
        }
        __syncthreads();
    }

    float v = (tid < T) ? sc[tid] : -FLT_MAX;
#pragma unroll
    for (int o = 16; o > 0; o >>= 1) v = fmaxf(v, __shfl_xor_sync(0xffffffffu, v, o));
    if ((tid & 31) == 0) red[tid >> 5] = v;
    __syncthreads();
    if (tid == 0) {
        float mx = red[0];
#pragma unroll
        for (int w = 1; w < 10; w++) mx = fmaxf(mx, red[w]);
        red[12] = mx;
    }
    __syncthreads();
    float mx = red[12];

    float e = (tid < T) ? __expf(sc[tid] - mx) : 0.0f;
    float s = e;
#pragma unroll
    for (int o = 16; o > 0; o >>= 1) s += __shfl_xor_sync(0xffffffffu, s, o);
    __syncthreads();
    if ((tid & 31) == 0) red[tid >> 5] = s;
    __syncthreads();
    if (tid == 0) {
        float sum = 0.0f;
#pragma unroll
        for (int w = 0; w < 10; w++) sum += red[w];
        red[13] = 1.0f / sum;
    }
    __syncthreads();
    if (tid < T) alpha[(size_t)b * T + tid] = e * red[13];
}

// ======================================================================
// FCN head + hist_sum (unchanged).
// ======================================================================
__global__ void fcn_kernel(const int* __restrict__ u, const int* __restrict__ ii,
                           const int* __restrict__ hist_i,
                           const float* __restrict__ item_emb,
                           const float* __restrict__ user_emb,
                           const float* __restrict__ final2,
                           const float* __restrict__ W1, const float* __restrict__ b1,
                           const float* __restrict__ p1,
                           const float* __restrict__ W2, const float* __restrict__ b2,
                           const float* __restrict__ p2,
                           const float* __restrict__ W3, const float* __restrict__ b3,
                           float* __restrict__ out)
{
    __shared__ float xs[320];
    __shared__ float h1s[128];
    __shared__ float h2s[40];

    const int b = blockIdx.x;
    const int tid = threadIdx.x;

    if (tid < 64) {
        const int* hi = hist_i + (size_t)b * T;
        float s0 = 0.f, s1 = 0.f, s2 = 0.f, s3 = 0.f;
        for (int t = 0; t < T; t += 4) {
            s0 += item_emb[(size_t)hi[t]     * 64 + tid];
            s1 += item_emb[(size_t)hi[t + 1] * 64 + tid];
            s2 += item_emb[(size_t)hi[t + 2] * 64 + tid];
            s3 += item_emb[(size_t)hi[t + 3] * 64 + tid];
        }
        xs[128 + tid] = (s0 + s1) + (s2 + s3);
    } else {
        int j = tid - 64;
        xs[j]       = user_emb[(size_t)u[b]  * 64 + j];
        xs[64 + j]  = item_emb[(size_t)ii[b] * 64 + j];
        xs[256 + j] = final2[(size_t)b * 64 + j];
    }
    __syncthreads();
    if (tid < 64) xs[192 + tid] = xs[64 + tid] * xs[128 + tid];
    __syncthreads();

    {
        float a0 = b1[tid], a1 = 0.0f;
#pragma unroll 8
        for (int k = 0; k < 320; k += 2) {
            a0 = fmaf(xs[k],     W1[k * 128 + tid],       a0);
            a1 = fmaf(xs[k + 1], W1[(k + 1) * 128 + tid], a1);
        }
        float h = a0 + a1;
        h1s[tid] = (h >= 0.0f) ? h : p1[tid] * h;
    }
    __syncthreads();

    if (tid < 40) {
        float a0 = b2[tid], a1 = 0.0f;
#pragma unroll 16
        for (int k = 0; k < 128; k += 2) {
            a0 = fmaf(h1s[k],     W2[k * 40 + tid],       a0);
            a1 = fmaf(h1s[k + 1], W2[(k + 1) * 40 + tid], a1);
        }
        float h = a0 + a1;
        h2s[tid] = (h >= 0.0f) ? h : p2[tid] * h;
    }
    __syncthreads();

    if (tid == 0) {
        float acc = b3[0];
#pragma unroll
        for (int k = 0; k < 40; k++) acc = fmaf(h2s[k], W3[k], acc);
        out[b] = acc;
    }
}

// ======================================================================
extern "C" void kernel_launch(void* const* d_in, const int* in_sizes, int n_in,
                              void* d_out, int out_size)
{
    const int*   u        = (const int*)d_in[0];
    const int*   ii       = (const int*)d_in[1];
    const int*   hist_i   = (const int*)d_in[2];
    const float* mask     = (const float*)d_in[3];
    const float* item_emb = (const float*)d_in[4];
    const float* user_emb = (const float*)d_in[5];
    const float* g1_Wg = (const float*)d_in[6];
    const float* g1_Ug = (const float*)d_in[7];
    const float* g1_bg = (const float*)d_in[8];
    const float* g1_Wc = (const float*)d_in[9];
    const float* g1_Uc = (const float*)d_in[10];
    const float* g1_bc = (const float*)d_in[11];
    const float* Wa1 = (const float*)d_in[12];
    const float* ba1 = (const float*)d_in[13];
    const float* Wa2 = (const float*)d_in[14];
    const float* ba2 = (const float*)d_in[15];
    const float* Wa3 = (const float*)d_in[16];
    const float* ba3 = (const float*)d_in[17];
    const float* g2_Wg = (const float*)d_in[18];
    const float* g2_Ug = (const float*)d_in[19];
    const float* g2_bg = (const float*)d_in[20];
    const float* g2_Wc = (const float*)d_in[21];
    const float* g2_Uc = (const float*)d_in[22];
    const float* g2_bc = (const float*)d_in[23];
    const float* W1 = (const float*)d_in[24];
    const float* b1 = (const float*)d_in[25];
    const float* p1 = (const float*)d_in[26];
    const float* W2 = (const float*)d_in[27];
    const float* b2 = (const float*)d_in[28];
    const float* p2 = (const float*)d_in[29];
    const float* W3 = (const float*)d_in[30];
    const float* b3 = (const float*)d_in[31];
    float* out = (float*)d_out;

    float *xg, *xc, *rnn1, *alpha, *final2;
    __nv_bfloat16 *bh1, *bl1, *bh2, *bl2;
    cudaGetSymbolAddress((void**)&xg,     g_xg);
    cudaGetSymbolAddress((void**)&xc,     g_xc);
    cudaGetSymbolAddress((void**)&rnn1,   g_rnn1);
    cudaGetSymbolAddress((void**)&alpha,  g_alpha);
    cudaGetSymbolAddress((void**)&final2, g_final2);
    cudaGetSymbolAddress((void**)&bh1, g_bh1);
    cudaGetSymbolAddress((void**)&bl1, g_bl1);
    cudaGetSymbolAddress((void**)&bh2, g_bh2);
    cudaGetSymbolAddress((void**)&bl2, g_bl2);

    const int GRU_SMEM  = (128 * 68 + 64 * 68 + 3 * NP * 128 + GR * T) * 4;  // 67904
    const int ATTN_SMEM = (64*80 + 80 + 80*40 + 40 + 40 + 64
                         + 32*68 + 32*80 + 32*40 + 224 + 16) * 4;

    cudaFuncSetAttribute(proj_mma_kernel<0>, cudaFuncAttributeMaxDynamicSharedMemorySize, PSM_TOTAL);
    cudaFuncSetAttribute(proj_mma_kernel<1>, cudaFuncAttributeMaxDynamicSharedMemorySize, PSM_TOTAL);
    cudaFuncSetAttribute(gru_kernel<true>,  cudaFuncAttributeMaxDynamicSharedMemorySize, GRU_SMEM);
    cudaFuncSetAttribute(gru_kernel<false>, cudaFuncAttributeMaxDynamicSharedMemorySize, GRU_SMEM);
    cudaFuncSetAttribute(attn_kernel, cudaFuncAttributeMaxDynamicSharedMemorySize, ATTN_SMEM);

    const int GRU_GRID = (B + GR - 1) / GR;   // 410

    // 0) split projection weights to bf16 hi/lo (both GRUs)
    wsplit_kernel<<<48, 256>>>(g1_Wg, g1_Wc, bh1, bl1);
    wsplit_kernel<<<48, 256>>>(g2_Wg, g2_Wc, bh2, bl2);
    // 1) GRU1 input projections via HMMA tensor cores
    proj_mma_kernel<0><<<BT / 128, 256, PSM_TOTAL>>>(item_emb, hist_i, nullptr,
                                                     bh1, bl1, g1_bg, g1_bc, xg, xc);
    // 2) GRU1 recurrence -> rnn1
    gru_kernel<true><<<GRU_GRID, 128, GRU_SMEM>>>(xg, xc, mask, g1_Ug, g1_Uc, rnn1);
    // 3) DIN attention -> alpha
    attn_kernel<<<B, 320, ATTN_SMEM>>>(ii, item_emb, rnn1, mask,
                                       Wa1, ba1, Wa2, ba2, Wa3, ba3, alpha);
    // 4) GRU2 input projections via HMMA (rnn1 * alpha)
    proj_mma_kernel<1><<<BT / 128, 256, PSM_TOTAL>>>(rnn1, nullptr, alpha,
                                                     bh2, bl2, g2_bg, g2_bc, xg, xc);
    // 5) GRU2 recurrence -> final2 only
    gru_kernel<false><<<GRU_GRID, 128, GRU_SMEM>>>(xg, xc, mask, g2_Ug, g2_Uc, final2);
    // 6) FCN head -> logits
    fcn_kernel<<<B, 128>>>(u, ii, hist_i, item_emb, user_emb, final2,
                           W1, b1, p1, W2, b2, p2, W3, b3, out);
}